// round 6
// baseline (speedup 1.0000x reference)
#include <cuda_runtime.h>
#include <cuda_fp16.h>
#include <cstdint>

#define Bb 8
#define Nn 4096
#define Mm 1024

// ---------------------------------------------------------------------------
// Scratch (device globals) — pre-swizzled images for flat bulk copies
// ---------------------------------------------------------------------------
__device__ __half g_qh[Bb*Nn*64];    // Q hi fp16, per-64-row-chunk swizzled images
__device__ __half g_ql[Bb*Nn*64];    // Q lo fp16
__device__ __half g_kh[Bb*Mm*64];    // K hi fp16, per-64-key-tile images ([key][d])
__device__ __half g_kl[Bb*Mm*64];    // K lo fp16
__device__ __half g_qaug[Bb*Nn*24];  // Q-side RBF aug rows (24 halfs = 48B each)
__device__ __half g_kaug[Bb*Mm*24];  // K-side RBF aug rows
__device__ float  g_vT[Bb*Mm*64];    // V^T tf32, per-64-key-tile images ([d][key])
__device__ float  g_kern[Bb*Nn*64];  // attention output [b][n][d]

#define LOG_THRESH (-2.99573227355399f)   // ln(0.05)

// ---------------------------------------------------------------------------
// Helpers
// ---------------------------------------------------------------------------
__device__ __forceinline__ uint32_t smem_u32(const void* p) {
    uint32_t a;
    asm("{ .reg .u64 t; cvta.to.shared.u64 t, %1; cvt.u32.u64 %0, t; }" : "=r"(a) : "l"(p));
    return a;
}
__device__ __forceinline__ float tf32_rna(float x) {
    uint32_t u;
    asm("cvt.rna.tf32.f32 %0, %1;" : "=r"(u) : "f"(x));
    return __uint_as_float(u);
}

#define MBAR_INIT(a, c) asm volatile("mbarrier.init.shared.b64 [%0], %1;" :: "r"(a), "r"((uint32_t)(c)) : "memory")
#define MBAR_EXPECT(a, b) asm volatile("mbarrier.arrive.expect_tx.shared.b64 _, [%0], %1;" :: "r"(a), "r"((uint32_t)(b)) : "memory")
#define MBAR_WAIT(a, ph) do { \
    asm volatile("{ .reg .pred P1; WL_%=: mbarrier.try_wait.parity.acquire.cta.shared::cta.b64 P1, [%0], %1, 0x989680; @P1 bra.uni WD_%=; bra.uni WL_%=; WD_%=: }" \
        :: "r"(a), "r"((uint32_t)(ph)) : "memory"); } while (0)

__device__ __forceinline__ void bulk_cp(uint32_t dst, const void* src, uint32_t bytes, uint32_t mbar) {
    asm volatile("cp.async.bulk.shared::cta.global.mbarrier::complete_tx::bytes [%0], [%1], %2, [%3];"
        :: "r"(dst), "l"(src), "r"(bytes), "r"(mbar) : "memory");
}

__device__ __forceinline__ void ldsm4(uint32_t r[4], uint32_t a) {
    asm volatile("ldmatrix.sync.aligned.m8n8.x4.shared.b16 {%0,%1,%2,%3}, [%4];"
        : "=r"(r[0]), "=r"(r[1]), "=r"(r[2]), "=r"(r[3]) : "r"(a));
}

__device__ __forceinline__ void mma_tf32(float c[4], const uint32_t a[4], const uint32_t b[2]) {
    asm volatile("mma.sync.aligned.m16n8k8.row.col.f32.tf32.tf32.f32 "
        "{%0,%1,%2,%3}, {%4,%5,%6,%7}, {%8,%9}, {%0,%1,%2,%3};"
        : "+f"(c[0]), "+f"(c[1]), "+f"(c[2]), "+f"(c[3])
        : "r"(a[0]), "r"(a[1]), "r"(a[2]), "r"(a[3]), "r"(b[0]), "r"(b[1]));
}
__device__ __forceinline__ void mma_f16(float c[4], const uint32_t a[4], const uint32_t b[2]) {
    asm volatile("mma.sync.aligned.m16n8k16.row.col.f32.f16.f16.f32 "
        "{%0,%1,%2,%3}, {%4,%5,%6,%7}, {%8,%9}, {%0,%1,%2,%3};"
        : "+f"(c[0]), "+f"(c[1]), "+f"(c[2]), "+f"(c[3])
        : "r"(a[0]), "r"(a[1]), "r"(a[2]), "r"(a[3]), "r"(b[0]), "r"(b[1]));
}

// ---------------------------------------------------------------------------
// RBF aug rows: r(n,m) = sum_i vQ_i * vK_i = -g*|x1-x2|^2
// vQ = [2g*x1, -g|x1|^2, 1], vK = [x2, 1, -g|x2|^2]
// Packed hi/lo trick: Qrow = [ah(5), al(5), ah(5), 0], Krow = [bh(5), bh(5), bl(5), 0]
// -> single k16 dot = ah.bh + al.bh + ah.bl
// ---------------------------------------------------------------------------
__global__ __launch_bounds__(256) void aug_kernel(
    const float* __restrict__ xyz1, const float* __restrict__ xyz2,
    const float* __restrict__ gammap)
{
    int gr = blockIdx.x * 256 + threadIdx.x;
    float g = gammap[0];
    float v[5];
    __half* dst;
    bool qside = gr < Bb*Nn;
    if (qside) {
        int b = gr >> 12, n = gr & (Nn-1);
        const float* xp = xyz1 + (size_t)gr*3;
        float x = xp[0], y = xp[1], z = xp[2];
        v[0] = 2.0f*g*x; v[1] = 2.0f*g*y; v[2] = 2.0f*g*z;
        v[3] = -g*(x*x + y*y + z*z); v[4] = 1.0f;
        int img = b*64 + (n >> 6), rr = n & 63;
        dst = g_qaug + (size_t)img*1536 + rr*24;
    } else {
        int gr2 = gr - Bb*Nn;
        if (gr2 >= Bb*Mm) return;
        int b = gr2 >> 10, m = gr2 & (Mm-1);
        const float* xp = xyz2 + (size_t)gr2*3;
        float x = xp[0], y = xp[1], z = xp[2];
        v[0] = x; v[1] = y; v[2] = z;
        v[3] = 1.0f; v[4] = -g*(x*x + y*y + z*z);
        int img = b*16 + (m >> 6), rr = m & 63;
        dst = g_kaug + (size_t)img*1536 + rr*24;
    }
    __half h[5], l[5];
#pragma unroll
    for (int i = 0; i < 5; i++) {
        h[i] = __float2half_rn(v[i]);
        l[i] = __float2half_rn(v[i] - __half2float(h[i]));
    }
    __half row[24];
#pragma unroll
    for (int i = 0; i < 24; i++) row[i] = __float2half_rn(0.0f);
#pragma unroll
    for (int i = 0; i < 5; i++) {
        row[i] = h[i];
        if (qside) { row[5+i] = l[i]; row[10+i] = h[i]; }
        else       { row[5+i] = h[i]; row[10+i] = l[i]; }
    }
    float4* d4 = (float4*)dst;
    const float4* s4 = (const float4*)row;
    d4[0] = s4[0]; d4[1] = s4[1]; d4[2] = s4[2];
}

// ---------------------------------------------------------------------------
// Projection GEMMs (SIMT): write swizzled GMEM images.
// MODE 0: Q fp16 hi/lo, 64-row-chunk images. MODE 1: K fp16 hi/lo tiles.
// MODE 2: V^T tf32 images.
// ---------------------------------------------------------------------------
template <int MODE>
__global__ __launch_bounds__(256) void proj_kernel(
    const float* __restrict__ A, const float* __restrict__ W,
    void* __restrict__ Cout_hi, void* __restrict__ Cout_lo)
{
    __shared__ float sA[64*64];
    __shared__ float sW[64*64];
    int tid = threadIdx.x;
    int rowbase = blockIdx.x * 64;

#pragma unroll
    for (int p = 0; p < 4; p++) {
        int lin = tid + 256*p;
        int r = lin >> 4, c4 = lin & 15;
        float4 av = *(const float4*)(A + (rowbase + r)*64 + c4*4);
        *(float4*)(sA + r*64 + ((c4 ^ (r & 15)) << 2)) = av;
        *(float4*)(sW + r*64 + (c4 << 2)) = *(const float4*)(W + r*64 + c4*4);
    }
    __syncthreads();

    int ty = tid >> 4, tx = tid & 15;
    int r0 = ty*4, c0 = tx*4;
    int rx[4], rb[4];
#pragma unroll
    for (int i = 0; i < 4; i++) { rx[i] = (r0+i) & 15; rb[i] = (r0+i)*64; }

    float acc[4][4] = {};
#pragma unroll
    for (int d4 = 0; d4 < 16; d4++) {
        float a[4][4], bb[4][4];
#pragma unroll
        for (int i = 0; i < 4; i++) {
            float4 t = *(const float4*)(sA + rb[i] + ((d4 ^ rx[i]) << 2));
            a[i][0]=t.x; a[i][1]=t.y; a[i][2]=t.z; a[i][3]=t.w;
        }
#pragma unroll
        for (int k = 0; k < 4; k++) {
            float4 t = *(const float4*)(sW + (d4*4+k)*64 + c0);
            bb[k][0]=t.x; bb[k][1]=t.y; bb[k][2]=t.z; bb[k][3]=t.w;
        }
#pragma unroll
        for (int k = 0; k < 4; k++)
#pragma unroll
            for (int i = 0; i < 4; i++)
#pragma unroll
                for (int j = 0; j < 4; j++)
                    acc[i][j] = fmaf(a[i][k], bb[k][j], acc[i][j]);
    }

#pragma unroll
    for (int i = 0; i < 4; i++) {
        int grow = rowbase + r0 + i;
        if (MODE <= 1) {
            int img = grow >> 6, rr = grow & 63;
            uint32_t swc = ((uint32_t)(c0 >> 3)) ^ (uint32_t)(rr & 7);
            uint32_t hoff = (uint32_t)rr*64u + swc*8u + (uint32_t)(c0 & 7);
            __half h[4], l[4];
#pragma unroll
            for (int j = 0; j < 4; j++) {
                h[j] = __float2half_rn(acc[i][j]);
                l[j] = __float2half_rn(acc[i][j] - __half2float(h[j]));
            }
            __half* ph = (__half*)Cout_hi + (size_t)img*4096 + hoff;
            __half* pl = (__half*)Cout_lo + (size_t)img*4096 + hoff;
            *(__half2*)(ph)     = __halves2half2(h[0], h[1]);
            *(__half2*)(ph + 2) = __halves2half2(h[2], h[3]);
            *(__half2*)(pl)     = __halves2half2(l[0], l[1]);
            *(__half2*)(pl + 2) = __halves2half2(l[2], l[3]);
        } else {
            int img = grow >> 6, kk = grow & 63;
#pragma unroll
            for (int j = 0; j < 4; j++) {
                int e = c0 + j;
                uint32_t off = (uint32_t)(e*64 + (((kk >> 2) ^ (e & 7)) << 2) + (kk & 3));
                ((float*)Cout_hi)[img*4096 + off] = tf32_rna(acc[i][j]);
            }
        }
    }
}

// ---------------------------------------------------------------------------
// Fused attention: 64 queries x 1024 keys per CTA, 8 warps, 2 CTAs/SM.
// MMA1: fp16 2-split S (3 passes) + packed RBF aug accumulator (1 step).
// MMA2 (PV): tf32. Q fragments preloaded to registers once.
// ---------------------------------------------------------------------------
#define SM_P      0u          // 16KB: P tf32 tile; staging for QH(0)/QL(8192) at start
#define SM_QAUG   16384u      // 3072B Q aug rows (48B stride)
#define SM_BUF0   19456u
#define BUF_KH    0u          // 8KB fp16
#define BUF_KL    8192u       // 8KB fp16
#define BUF_KAUG  16384u      // 3072B aug rows
#define BUF_V     19456u      // 16KB tf32
#define BUF_BYTES 35840u
#define SM_BUF1   (SM_BUF0 + BUF_BYTES)
#define SM_TOTAL  (SM_BUF1 + BUF_BYTES)   // 91136

__global__ __launch_bounds__(256, 2) void attn_mma_kernel()
{
    extern __shared__ char dyn[];
    __shared__ __align__(8) uint64_t mbars[2];
    __shared__ float sDen[2][64];

    uint32_t sb = smem_u32(dyn);
    int tid = threadIdx.x, lane = tid & 31, wid = tid >> 5;
    int wm = wid & 3, wn = wid >> 2;
    int bI = blockIdx.y, nbase = blockIdx.x * 64;

    uint32_t mb[2] = { smem_u32(&mbars[0]), smem_u32(&mbars[1]) };
    if (tid == 0) { MBAR_INIT(mb[0], 1); MBAR_INIT(mb[1], 1); }
    __syncthreads();

    if (tid == 0) {
        int img = bI * 16;
        int qimg = bI*64 + blockIdx.x;
        MBAR_EXPECT(mb[0], 8192u*2 + 3072u + BUF_BYTES);
        bulk_cp(sb + SM_P,         g_qh   + (size_t)qimg*4096, 8192, mb[0]);
        bulk_cp(sb + SM_P + 8192,  g_ql   + (size_t)qimg*4096, 8192, mb[0]);
        bulk_cp(sb + SM_QAUG,      g_qaug + (size_t)qimg*1536, 3072, mb[0]);
        bulk_cp(sb + SM_BUF0 + BUF_KH,   g_kh   + (size_t)img*4096, 8192, mb[0]);
        bulk_cp(sb + SM_BUF0 + BUF_KL,   g_kl   + (size_t)img*4096, 8192, mb[0]);
        bulk_cp(sb + SM_BUF0 + BUF_KAUG, g_kaug + (size_t)img*1536, 3072, mb[0]);
        bulk_cp(sb + SM_BUF0 + BUF_V,    g_vT   + (size_t)img*4096, 16384, mb[0]);
        MBAR_EXPECT(mb[1], BUF_BYTES);
        bulk_cp(sb + SM_BUF1 + BUF_KH,   g_kh   + (size_t)(img+1)*4096, 8192, mb[1]);
        bulk_cp(sb + SM_BUF1 + BUF_KL,   g_kl   + (size_t)(img+1)*4096, 8192, mb[1]);
        bulk_cp(sb + SM_BUF1 + BUF_KAUG, g_kaug + (size_t)(img+1)*1536, 3072, mb[1]);
        bulk_cp(sb + SM_BUF1 + BUF_V,    g_vT   + (size_t)(img+1)*4096, 16384, mb[1]);
    }

    // fragment addressing
    uint32_t frowA = (uint32_t)((lane & 7) + (((lane >> 3) & 1) << 3));
    uint32_t fchkA = (uint32_t)(lane >> 4);
    uint32_t frowB = (uint32_t)((lane & 7) + ((lane >> 4) << 3));
    uint32_t fchkB = (uint32_t)((lane >> 3) & 1);
    uint32_t fsw   = (uint32_t)(lane & 7);

    // ---- preload Q fragments (whole kernel) ----
    MBAR_WAIT(mb[0], 0);
    uint32_t qh[4][4], ql[4][4], qaug[4];
    {
        uint32_t qrow = (uint32_t)(wm*16) + frowA;
#pragma unroll
        for (int s = 0; s < 4; s++) {
            uint32_t chunk = ((uint32_t)(2*s) + fchkA) ^ fsw;
            ldsm4(qh[s], sb + SM_P +         qrow*128u + (chunk << 4));
            ldsm4(ql[s], sb + SM_P + 8192u + qrow*128u + (chunk << 4));
        }
        ldsm4(qaug, sb + SM_QAUG + ((uint32_t)(wm*16) + frowA)*48u + fchkA*16u);
    }
    __syncthreads();   // Q staging read by all warps before P overwrites it

    float oacc[4][4] = {};
    float dsum[2] = {};

    for (int t = 0; t < 16; t++) {
        int idx = t & 1;
        uint32_t bufb = sb + (idx ? SM_BUF1 : SM_BUF0);
        if (t) MBAR_WAIT(mb[idx], (t >> 1) & 1);

        // ---- MMA1: S (3-pass fp16 split) + R (packed aug, 1 step) ----
        float sacc[4][4] = {};
        float racc[4][4] = {};
        uint32_t krow0 = (uint32_t)(wn*32) + frowB;
#pragma unroll
        for (int s = 0; s < 4; s++) {
            uint32_t chunk = ((uint32_t)(2*s) + fchkB) ^ fsw;
            uint32_t kh2[2][4], kl2[2][4];
            ldsm4(kh2[0], bufb + BUF_KH + krow0*128u + (chunk << 4));
            ldsm4(kh2[1], bufb + BUF_KH + (krow0 + 16u)*128u + (chunk << 4));
            ldsm4(kl2[0], bufb + BUF_KL + krow0*128u + (chunk << 4));
            ldsm4(kl2[1], bufb + BUF_KL + (krow0 + 16u)*128u + (chunk << 4));
#pragma unroll
            for (int fn = 0; fn < 4; fn++) {
                mma_f16(sacc[fn], qh[s], &kh2[fn>>1][2*(fn&1)]);
                mma_f16(sacc[fn], qh[s], &kl2[fn>>1][2*(fn&1)]);
                mma_f16(sacc[fn], ql[s], &kh2[fn>>1][2*(fn&1)]);
            }
        }
        {
            uint32_t ka[2][4];
            ldsm4(ka[0], bufb + BUF_KAUG + krow0*48u + fchkB*16u);
            ldsm4(ka[1], bufb + BUF_KAUG + (krow0 + 16u)*48u + fchkB*16u);
#pragma unroll
            for (int fn = 0; fn < 4; fn++)
                mma_f16(racc[fn], qaug, &ka[fn>>1][2*(fn&1)]);
        }

        // ---- epilogue: S,R -> P, dsum ----
#pragma unroll
        for (int fn = 0; fn < 4; fn++) {
            int colb = wn*32 + fn*8 + 2*(lane & 3);
#pragma unroll
            for (int h = 0; h < 2; h++) {
                float s0 = sacc[fn][2*h+0];
                float s1 = sacc[fn][2*h+1];
                float r0 = racc[fn][2*h+0];
                float r1 = racc[fn][2*h+1];
                float e20 = __expf(s0);
                float e21 = __expf(s1);
                dsum[h] += e20 + e21;
                float2 pv;
                pv.x = tf32_rna((r0 > LOG_THRESH) ? __expf(s0 + r0) : 0.0f);
                pv.y = tf32_rna((r1 > LOG_THRESH) ? __expf(s1 + r1) : 0.0f);
                int row = wm*16 + (lane >> 2) + 8*h;
                uint32_t pa = SM_P + (uint32_t)row*256u
                            + ((((uint32_t)colb >> 2) ^ (uint32_t)(lane >> 2)) << 4)
                            + ((uint32_t)colb & 3u)*4u;
                *(float2*)(dyn + pa) = pv;
            }
        }
        __syncthreads();

        // ---- MMA2: O += P * V (tf32, 8 k8 steps) ----
        uint32_t prow = (uint32_t)(wm*16) + frowA;
        uint32_t vrow0 = (uint32_t)(wn*32) + frowB;
#pragma unroll
        for (int s = 0; s < 8; s++) {
            uint32_t chunkA = ((uint32_t)(2*s) + fchkA) ^ fsw;
            uint32_t chunkB = ((uint32_t)(2*s) + fchkB) ^ fsw;
            uint32_t pf[4], v2[2][4];
            ldsm4(pf, sb + SM_P + prow*256u + (chunkA << 4));
            ldsm4(v2[0], bufb + BUF_V + vrow0*256u + (chunkB << 4));
            ldsm4(v2[1], bufb + BUF_V + (vrow0 + 16u)*256u + (chunkB << 4));
#pragma unroll
            for (int fn = 0; fn < 4; fn++)
                mma_tf32(oacc[fn], pf, &v2[fn>>1][2*(fn&1)]);
        }
        __syncthreads();

        // prefetch tile t+2 into the buffer just freed
        if (t < 14 && tid == 0) {
            int img = bI*16 + t + 2;
            uint32_t dstb = sb + (idx ? SM_BUF1 : SM_BUF0);
            MBAR_EXPECT(mb[idx], BUF_BYTES);
            bulk_cp(dstb + BUF_KH,   g_kh   + (size_t)img*4096, 8192, mb[idx]);
            bulk_cp(dstb + BUF_KL,   g_kl   + (size_t)img*4096, 8192, mb[idx]);
            bulk_cp(dstb + BUF_KAUG, g_kaug + (size_t)img*1536, 3072, mb[idx]);
            bulk_cp(dstb + BUF_V,    g_vT   + (size_t)img*4096, 16384, mb[idx]);
        }
    }

    // ---- denominator reduction (4 lanes share each row) ----
#pragma unroll
    for (int off = 1; off < 4; off <<= 1)
#pragma unroll
        for (int h = 0; h < 2; h++)
            dsum[h] += __shfl_xor_sync(0xFFFFFFFFu, dsum[h], off);
    if ((lane & 3) == 0)
#pragma unroll
        for (int h = 0; h < 2; h++)
            sDen[wn][wm*16 + (lane >> 2) + 8*h] = dsum[h];
    __syncthreads();

    float inv[2];
#pragma unroll
    for (int h = 0; h < 2; h++) {
        int row = wm*16 + (lane >> 2) + 8*h;
        inv[h] = 1.0f / (sDen[0][row] + sDen[1][row]);
    }

    // ---- normalize + store ----
#pragma unroll
    for (int fn = 0; fn < 4; fn++) {
        int colb = wn*32 + fn*8 + 2*(lane & 3);
#pragma unroll
        for (int h = 0; h < 2; h++) {
            int row = wm*16 + (lane >> 2) + 8*h;
            float2 o;
            o.x = oacc[fn][2*h+0] * inv[h];
            o.y = oacc[fn][2*h+1] * inv[h];
            *(float2*)(g_kern + ((size_t)bI*Nn + nbase + row)*64 + colb) = o;
        }
    }
}

// ---------------------------------------------------------------------------
// Output MLP: out = relu(concat(points1, kern) @ Wo + bo)
// ---------------------------------------------------------------------------
__global__ __launch_bounds__(256) void mlp_kernel(
    const float* __restrict__ p1, const float* __restrict__ Wo,
    const float* __restrict__ bo, float* __restrict__ out)
{
    __shared__ float sA[64*64];
    __shared__ float sB[64*128];
    int tid = threadIdx.x;
    int rowbase = blockIdx.x * 64;
    int ty = tid >> 4, tx = tid & 15;
    int r0 = ty*4, c0 = tx*4;
    int rx[4], rb[4];
#pragma unroll
    for (int i = 0; i < 4; i++) { rx[i] = (r0+i) & 15; rb[i] = (r0+i)*64; }

    float acc[4][8] = {};
#pragma unroll 1
    for (int ch = 0; ch < 2; ch++) {
        const float* Asrc = ch ? (const float*)g_kern : p1;
        __syncthreads();
#pragma unroll
        for (int p = 0; p < 4; p++) {
            int lin = tid + 256*p;
            int r = lin >> 4, c4 = lin & 15;
            float4 t = *(const float4*)(Asrc + (rowbase + r)*64 + c4*4);
            *(float4*)(sA + r*64 + ((c4 ^ (r & 15)) << 2)) = t;
        }
#pragma unroll
        for (int p = 0; p < 8; p++) {
            int lin = tid + 256*p;
            int r = lin >> 5, c4 = lin & 31;
            *(float4*)(sB + r*128 + c4*4) = *(const float4*)(Wo + (ch*64 + r)*128 + c4*4);
        }
        __syncthreads();

#pragma unroll
        for (int d4 = 0; d4 < 16; d4++) {
            float a[4][4], b1[4][4], b2[4][4];
#pragma unroll
            for (int i = 0; i < 4; i++) {
                float4 t = *(const float4*)(sA + rb[i] + ((d4 ^ rx[i]) << 2));
                a[i][0]=t.x; a[i][1]=t.y; a[i][2]=t.z; a[i][3]=t.w;
            }
#pragma unroll
            for (int k = 0; k < 4; k++) {
                float4 t = *(const float4*)(sB + (d4*4+k)*128 + c0);
                b1[k][0]=t.x; b1[k][1]=t.y; b1[k][2]=t.z; b1[k][3]=t.w;
                float4 u = *(const float4*)(sB + (d4*4+k)*128 + 64 + c0);
                b2[k][0]=u.x; b2[k][1]=u.y; b2[k][2]=u.z; b2[k][3]=u.w;
            }
#pragma unroll
            for (int k = 0; k < 4; k++)
#pragma unroll
                for (int i = 0; i < 4; i++)
#pragma unroll
                    for (int j = 0; j < 4; j++) {
                        acc[i][j]   = fmaf(a[i][k], b1[k][j], acc[i][j]);
                        acc[i][4+j] = fmaf(a[i][k], b2[k][j], acc[i][4+j]);
                    }
        }
    }

    float bov[8];
#pragma unroll
    for (int j = 0; j < 4; j++) { bov[j] = bo[c0+j]; bov[4+j] = bo[64+c0+j]; }
#pragma unroll
    for (int i = 0; i < 4; i++) {
        int grow = rowbase + r0 + i;
        float4 o1, o2;
        o1.x = fmaxf(acc[i][0]+bov[0], 0.0f);
        o1.y = fmaxf(acc[i][1]+bov[1], 0.0f);
        o1.z = fmaxf(acc[i][2]+bov[2], 0.0f);
        o1.w = fmaxf(acc[i][3]+bov[3], 0.0f);
        o2.x = fmaxf(acc[i][4]+bov[4], 0.0f);
        o2.y = fmaxf(acc[i][5]+bov[5], 0.0f);
        o2.z = fmaxf(acc[i][6]+bov[6], 0.0f);
        o2.w = fmaxf(acc[i][7]+bov[7], 0.0f);
        *(float4*)(out + grow*128 + c0) = o1;
        *(float4*)(out + grow*128 + 64 + c0) = o2;
    }
}

// ---------------------------------------------------------------------------
extern "C" void kernel_launch(void* const* d_in, const int* in_sizes, int n_in,
                              void* d_out, int out_size)
{
    const float* xyz1 = (const float*)d_in[0];
    const float* xyz2 = (const float*)d_in[1];
    const float* p1   = (const float*)d_in[2];
    const float* p2   = (const float*)d_in[3];
    const float* Wq   = (const float*)d_in[4];
    const float* Wk   = (const float*)d_in[5];
    const float* Wv   = (const float*)d_in[6];
    const float* gm   = (const float*)d_in[7];
    const float* Wo   = (const float*)d_in[8];
    const float* bo   = (const float*)d_in[9];
    float* out = (float*)d_out;

    void *dqh, *dql, *dkh, *dkl, *dvT;
    cudaGetSymbolAddress(&dqh, g_qh);
    cudaGetSymbolAddress(&dql, g_ql);
    cudaGetSymbolAddress(&dkh, g_kh);
    cudaGetSymbolAddress(&dkl, g_kl);
    cudaGetSymbolAddress(&dvT, g_vT);

    aug_kernel<<<(Bb*Nn + Bb*Mm + 255)/256, 256>>>(xyz1, xyz2, gm);
    proj_kernel<0><<<(Bb*Nn)/64, 256>>>(p1, Wq, dqh, dql);
    proj_kernel<1><<<(Bb*Mm)/64, 256>>>(p2, Wk, dkh, dkl);
    proj_kernel<2><<<(Bb*Mm)/64, 256>>>(p2, Wv, dvT, nullptr);

    cudaFuncSetAttribute(attn_mma_kernel, cudaFuncAttributeMaxDynamicSharedMemorySize, SM_TOTAL);
    attn_mma_kernel<<<dim3(Nn/64, Bb), 256, SM_TOTAL>>>();

    mlp_kernel<<<(Bb*Nn)/64, 256>>>(p1, Wo, bo, out);
}

// round 7
// speedup vs baseline: 1.0717x; 1.0717x over previous
#include <cuda_runtime.h>
#include <cuda_fp16.h>
#include <cstdint>

#define Bb 8
#define Nn 4096
#define Mm 1024

// ---------------------------------------------------------------------------
// Scratch (device globals) — pre-swizzled images for flat bulk copies
// ---------------------------------------------------------------------------
__device__ __half g_qh[Bb*Nn*64];    // Q hi fp16, per-64-row-chunk swizzled images
__device__ __half g_ql[Bb*Nn*64];    // Q lo fp16
__device__ __half g_kh[Bb*Mm*64];    // K hi fp16, per-64-key-tile images ([key][d])
__device__ __half g_kl[Bb*Mm*64];    // K lo fp16
__device__ __half g_qaug[Bb*Nn*24];  // Q-side RBF aug rows (24 halfs = 48B each)
__device__ __half g_kaug[Bb*Mm*24];  // K-side RBF aug rows
__device__ float  g_vT[Bb*Mm*64];    // V^T tf32, per-64-key-tile images ([d][key])
__device__ float  g_kern[Bb*Nn*64];  // attention output [b][n][d]

#define LOG_THRESH (-2.99573227355399f)   // ln(0.05)

// ---------------------------------------------------------------------------
// Helpers
// ---------------------------------------------------------------------------
__device__ __forceinline__ uint32_t smem_u32(const void* p) {
    uint32_t a;
    asm("{ .reg .u64 t; cvta.to.shared.u64 t, %1; cvt.u32.u64 %0, t; }" : "=r"(a) : "l"(p));
    return a;
}
__device__ __forceinline__ float tf32_rna(float x) {
    uint32_t u;
    asm("cvt.rna.tf32.f32 %0, %1;" : "=r"(u) : "f"(x));
    return __uint_as_float(u);
}

#define MBAR_INIT(a, c) asm volatile("mbarrier.init.shared.b64 [%0], %1;" :: "r"(a), "r"((uint32_t)(c)) : "memory")
#define MBAR_EXPECT(a, b) asm volatile("mbarrier.arrive.expect_tx.shared.b64 _, [%0], %1;" :: "r"(a), "r"((uint32_t)(b)) : "memory")
#define MBAR_WAIT(a, ph) do { \
    asm volatile("{ .reg .pred P1; WL_%=: mbarrier.try_wait.parity.acquire.cta.shared::cta.b64 P1, [%0], %1, 0x989680; @P1 bra.uni WD_%=; bra.uni WL_%=; WD_%=: }" \
        :: "r"(a), "r"((uint32_t)(ph)) : "memory"); } while (0)

__device__ __forceinline__ void bulk_cp(uint32_t dst, const void* src, uint32_t bytes, uint32_t mbar) {
    asm volatile("cp.async.bulk.shared::cta.global.mbarrier::complete_tx::bytes [%0], [%1], %2, [%3];"
        :: "r"(dst), "l"(src), "r"(bytes), "r"(mbar) : "memory");
}

__device__ __forceinline__ void ldsm4(uint32_t r[4], uint32_t a) {
    asm volatile("ldmatrix.sync.aligned.m8n8.x4.shared.b16 {%0,%1,%2,%3}, [%4];"
        : "=r"(r[0]), "=r"(r[1]), "=r"(r[2]), "=r"(r[3]) : "r"(a));
}

__device__ __forceinline__ void mma_tf32(float c[4], const uint32_t a[4], const uint32_t b[2]) {
    asm volatile("mma.sync.aligned.m16n8k8.row.col.f32.tf32.tf32.f32 "
        "{%0,%1,%2,%3}, {%4,%5,%6,%7}, {%8,%9}, {%0,%1,%2,%3};"
        : "+f"(c[0]), "+f"(c[1]), "+f"(c[2]), "+f"(c[3])
        : "r"(a[0]), "r"(a[1]), "r"(a[2]), "r"(a[3]), "r"(b[0]), "r"(b[1]));
}
__device__ __forceinline__ void mma_f16(float c[4], const uint32_t a[4], const uint32_t b[2]) {
    asm volatile("mma.sync.aligned.m16n8k16.row.col.f32.f16.f16.f32 "
        "{%0,%1,%2,%3}, {%4,%5,%6,%7}, {%8,%9}, {%0,%1,%2,%3};"
        : "+f"(c[0]), "+f"(c[1]), "+f"(c[2]), "+f"(c[3])
        : "r"(a[0]), "r"(a[1]), "r"(a[2]), "r"(a[3]), "r"(b[0]), "r"(b[1]));
}

// ---------------------------------------------------------------------------
// RBF aug rows (see R6): single k16 step gives ah.bh + al.bh + ah.bl = -g|x1-x2|^2
// ---------------------------------------------------------------------------
__global__ __launch_bounds__(256) void aug_kernel(
    const float* __restrict__ xyz1, const float* __restrict__ xyz2,
    const float* __restrict__ gammap)
{
    int gr = blockIdx.x * 256 + threadIdx.x;
    float g = gammap[0];
    float v[5];
    __half* dst;
    bool qside = gr < Bb*Nn;
    if (qside) {
        int b = gr >> 12, n = gr & (Nn-1);
        const float* xp = xyz1 + (size_t)gr*3;
        float x = xp[0], y = xp[1], z = xp[2];
        v[0] = 2.0f*g*x; v[1] = 2.0f*g*y; v[2] = 2.0f*g*z;
        v[3] = -g*(x*x + y*y + z*z); v[4] = 1.0f;
        int img = b*64 + (n >> 6), rr = n & 63;
        dst = g_qaug + (size_t)img*1536 + rr*24;
    } else {
        int gr2 = gr - Bb*Nn;
        if (gr2 >= Bb*Mm) return;
        int b = gr2 >> 10, m = gr2 & (Mm-1);
        const float* xp = xyz2 + (size_t)gr2*3;
        float x = xp[0], y = xp[1], z = xp[2];
        v[0] = x; v[1] = y; v[2] = z;
        v[3] = 1.0f; v[4] = -g*(x*x + y*y + z*z);
        int img = b*16 + (m >> 6), rr = m & 63;
        dst = g_kaug + (size_t)img*1536 + rr*24;
    }
    __half h[5], l[5];
#pragma unroll
    for (int i = 0; i < 5; i++) {
        h[i] = __float2half_rn(v[i]);
        l[i] = __float2half_rn(v[i] - __half2float(h[i]));
    }
    __half row[24];
#pragma unroll
    for (int i = 0; i < 24; i++) row[i] = __float2half_rn(0.0f);
#pragma unroll
    for (int i = 0; i < 5; i++) {
        row[i] = h[i];
        if (qside) { row[5+i] = l[i]; row[10+i] = h[i]; }
        else       { row[5+i] = h[i]; row[10+i] = l[i]; }
    }
    float4* d4 = (float4*)dst;
    const float4* s4 = (const float4*)row;
    d4[0] = s4[0]; d4[1] = s4[1]; d4[2] = s4[2];
}

// ---------------------------------------------------------------------------
// Projection GEMMs (SIMT): write swizzled GMEM images (unchanged from R6).
// ---------------------------------------------------------------------------
template <int MODE>
__global__ __launch_bounds__(256) void proj_kernel(
    const float* __restrict__ A, const float* __restrict__ W,
    void* __restrict__ Cout_hi, void* __restrict__ Cout_lo)
{
    __shared__ float sA[64*64];
    __shared__ float sW[64*64];
    int tid = threadIdx.x;
    int rowbase = blockIdx.x * 64;

#pragma unroll
    for (int p = 0; p < 4; p++) {
        int lin = tid + 256*p;
        int r = lin >> 4, c4 = lin & 15;
        float4 av = *(const float4*)(A + (rowbase + r)*64 + c4*4);
        *(float4*)(sA + r*64 + ((c4 ^ (r & 15)) << 2)) = av;
        *(float4*)(sW + r*64 + (c4 << 2)) = *(const float4*)(W + r*64 + c4*4);
    }
    __syncthreads();

    int ty = tid >> 4, tx = tid & 15;
    int r0 = ty*4, c0 = tx*4;
    int rx[4], rb[4];
#pragma unroll
    for (int i = 0; i < 4; i++) { rx[i] = (r0+i) & 15; rb[i] = (r0+i)*64; }

    float acc[4][4] = {};
#pragma unroll
    for (int d4 = 0; d4 < 16; d4++) {
        float a[4][4], bb[4][4];
#pragma unroll
        for (int i = 0; i < 4; i++) {
            float4 t = *(const float4*)(sA + rb[i] + ((d4 ^ rx[i]) << 2));
            a[i][0]=t.x; a[i][1]=t.y; a[i][2]=t.z; a[i][3]=t.w;
        }
#pragma unroll
        for (int k = 0; k < 4; k++) {
            float4 t = *(const float4*)(sW + (d4*4+k)*64 + c0);
            bb[k][0]=t.x; bb[k][1]=t.y; bb[k][2]=t.z; bb[k][3]=t.w;
        }
#pragma unroll
        for (int k = 0; k < 4; k++)
#pragma unroll
            for (int i = 0; i < 4; i++)
#pragma unroll
                for (int j = 0; j < 4; j++)
                    acc[i][j] = fmaf(a[i][k], bb[k][j], acc[i][j]);
    }

#pragma unroll
    for (int i = 0; i < 4; i++) {
        int grow = rowbase + r0 + i;
        if (MODE <= 1) {
            int img = grow >> 6, rr = grow & 63;
            uint32_t swc = ((uint32_t)(c0 >> 3)) ^ (uint32_t)(rr & 7);
            uint32_t hoff = (uint32_t)rr*64u + swc*8u + (uint32_t)(c0 & 7);
            __half h[4], l[4];
#pragma unroll
            for (int j = 0; j < 4; j++) {
                h[j] = __float2half_rn(acc[i][j]);
                l[j] = __float2half_rn(acc[i][j] - __half2float(h[j]));
            }
            __half* ph = (__half*)Cout_hi + (size_t)img*4096 + hoff;
            __half* pl = (__half*)Cout_lo + (size_t)img*4096 + hoff;
            *(__half2*)(ph)     = __halves2half2(h[0], h[1]);
            *(__half2*)(ph + 2) = __halves2half2(h[2], h[3]);
            *(__half2*)(pl)     = __halves2half2(l[0], l[1]);
            *(__half2*)(pl + 2) = __halves2half2(l[2], l[3]);
        } else {
            int img = grow >> 6, kk = grow & 63;
#pragma unroll
            for (int j = 0; j < 4; j++) {
                int e = c0 + j;
                uint32_t off = (uint32_t)(e*64 + (((kk >> 2) ^ (e & 7)) << 2) + (kk & 3));
                ((float*)Cout_hi)[img*4096 + off] = tf32_rna(acc[i][j]);
            }
        }
    }
}

// ---------------------------------------------------------------------------
// Fused attention: 64 q x 1024 keys per CTA, 8 warps (4 wm x 2 wn), 2 CTAs/SM.
// MMA1: fp16 2-split + RBF aug accumulator.  P stays in REGISTERS (shuffled
// into tf32 A-fragments); MMA2 over warp's own 32 keys x full d=64.
// One __syncthreads per tile; wn-halves of O summed once at the end.
// ---------------------------------------------------------------------------
#define SM_QH     0u          // 8KB fp16 Q hi (persistent)
#define SM_QL     8192u       // 8KB fp16 Q lo
#define SM_QAUG   16384u      // 3072B Q aug rows (48B stride)
#define SM_BUF0   19456u
#define BUF_KH    0u          // 8KB fp16
#define BUF_KL    8192u       // 8KB fp16
#define BUF_KAUG  16384u      // 3072B aug rows
#define BUF_V     19456u      // 16KB tf32
#define BUF_BYTES 35840u
#define SM_BUF1   (SM_BUF0 + BUF_BYTES)
#define SM_TOTAL  (SM_BUF1 + BUF_BYTES)   // 91136
#define RED_STRIDE 68

__global__ __launch_bounds__(256, 2) void attn_mma_kernel()
{
    extern __shared__ char dyn[];
    __shared__ __align__(8) uint64_t mbars[2];
    __shared__ float sDen[2][64];

    uint32_t sb = smem_u32(dyn);
    int tid = threadIdx.x, lane = tid & 31, wid = tid >> 5;
    int wm = wid & 3, wn = wid >> 2;
    int bI = blockIdx.y, nbase = blockIdx.x * 64;

    uint32_t mb[2] = { smem_u32(&mbars[0]), smem_u32(&mbars[1]) };
    if (tid == 0) { MBAR_INIT(mb[0], 1); MBAR_INIT(mb[1], 1); }
    __syncthreads();

    if (tid == 0) {
        int img = bI * 16;
        int qimg = bI*64 + blockIdx.x;
        MBAR_EXPECT(mb[0], 8192u*2 + 3072u + BUF_BYTES);
        bulk_cp(sb + SM_QH,   g_qh   + (size_t)qimg*4096, 8192, mb[0]);
        bulk_cp(sb + SM_QL,   g_ql   + (size_t)qimg*4096, 8192, mb[0]);
        bulk_cp(sb + SM_QAUG, g_qaug + (size_t)qimg*1536, 3072, mb[0]);
        bulk_cp(sb + SM_BUF0 + BUF_KH,   g_kh   + (size_t)img*4096, 8192, mb[0]);
        bulk_cp(sb + SM_BUF0 + BUF_KL,   g_kl   + (size_t)img*4096, 8192, mb[0]);
        bulk_cp(sb + SM_BUF0 + BUF_KAUG, g_kaug + (size_t)img*1536, 3072, mb[0]);
        bulk_cp(sb + SM_BUF0 + BUF_V,    g_vT   + (size_t)img*4096, 16384, mb[0]);
        MBAR_EXPECT(mb[1], BUF_BYTES);
        bulk_cp(sb + SM_BUF1 + BUF_KH,   g_kh   + (size_t)(img+1)*4096, 8192, mb[1]);
        bulk_cp(sb + SM_BUF1 + BUF_KL,   g_kl   + (size_t)(img+1)*4096, 8192, mb[1]);
        bulk_cp(sb + SM_BUF1 + BUF_KAUG, g_kaug + (size_t)(img+1)*1536, 3072, mb[1]);
        bulk_cp(sb + SM_BUF1 + BUF_V,    g_vT   + (size_t)(img+1)*4096, 16384, mb[1]);
    }

    // fragment addressing
    uint32_t frowA = (uint32_t)((lane & 7) + (((lane >> 3) & 1) << 3));
    uint32_t fchkA = (uint32_t)(lane >> 4);
    uint32_t frowB = (uint32_t)((lane & 7) + ((lane >> 4) << 3));
    uint32_t fchkB = (uint32_t)((lane >> 3) & 1);
    uint32_t fsw   = (uint32_t)(lane & 7);

    // shuffle constants for S-accum -> tf32 A-frag permutation
    int jj = lane & 3;
    int srcA = (lane & ~3) | (jj >> 1);
    int srcB = srcA + 2;
    bool selOdd = (jj & 1) != 0;

    // ---- preload qaug only (4 regs) ----
    MBAR_WAIT(mb[0], 0);
    uint32_t qaug[4];
    ldsm4(qaug, sb + SM_QAUG + ((uint32_t)(wm*16) + frowA)*48u + fchkA*16u);

    float oacc[8][4] = {};
    float dsum[2] = {};

    uint32_t qrow = (uint32_t)(wm*16) + frowA;
    uint32_t krow0 = (uint32_t)(wn*32) + frowB;

    for (int t = 0; t < 16; t++) {
        int idx = t & 1;
        uint32_t bufb = sb + (idx ? SM_BUF1 : SM_BUF0);
        if (t) MBAR_WAIT(mb[idx], (t >> 1) & 1);

        // ---- MMA1: S (3-pass fp16 split) + R (aug, 1 step) ----
        float sacc[4][4] = {};
        float racc[4][4] = {};
#pragma unroll
        for (int s = 0; s < 4; s++) {
            uint32_t chA = ((uint32_t)(2*s) + fchkA) ^ fsw;
            uint32_t chB = ((uint32_t)(2*s) + fchkB) ^ fsw;
            uint32_t qh_f[4], ql_f[4], kh2[2][4], kl2[2][4];
            ldsm4(qh_f, sb + SM_QH + qrow*128u + (chA << 4));
            ldsm4(ql_f, sb + SM_QL + qrow*128u + (chA << 4));
            ldsm4(kh2[0], bufb + BUF_KH + krow0*128u + (chB << 4));
            ldsm4(kh2[1], bufb + BUF_KH + (krow0 + 16u)*128u + (chB << 4));
            ldsm4(kl2[0], bufb + BUF_KL + krow0*128u + (chB << 4));
            ldsm4(kl2[1], bufb + BUF_KL + (krow0 + 16u)*128u + (chB << 4));
#pragma unroll
            for (int fn = 0; fn < 4; fn++) {
                mma_f16(sacc[fn], qh_f, &kh2[fn>>1][2*(fn&1)]);
                mma_f16(sacc[fn], qh_f, &kl2[fn>>1][2*(fn&1)]);
                mma_f16(sacc[fn], ql_f, &kh2[fn>>1][2*(fn&1)]);
            }
        }
        {
            uint32_t ka[2][4];
            ldsm4(ka[0], bufb + BUF_KAUG + krow0*48u + fchkB*16u);
            ldsm4(ka[1], bufb + BUF_KAUG + (krow0 + 16u)*48u + fchkB*16u);
#pragma unroll
            for (int fn = 0; fn < 4; fn++)
                mma_f16(racc[fn], qaug, &ka[fn>>1][2*(fn&1)]);
        }

        // ---- epilogue: S,R -> P (registers, tf32-rounded), dsum ----
        uint32_t parr[4][4];
#pragma unroll
        for (int fn = 0; fn < 4; fn++) {
#pragma unroll
            for (int e = 0; e < 4; e++) {
                float s = sacc[fn][e];
                float r = racc[fn][e];
                float e2 = __expf(s);
                dsum[(e >> 1)] += e2;
                float pv = (r > LOG_THRESH) ? __expf(s + r) : 0.0f;
                parr[fn][e] = __float_as_uint(tf32_rna(pv));
            }
        }

        // ---- MMA2: O += P * V, P from registers via quad shuffles ----
#pragma unroll
        for (int f = 0; f < 4; f++) {
            uint32_t af[4];
            {
                uint32_t t0, t1;
                t0 = __shfl_sync(0xFFFFFFFFu, parr[f][0], srcA);
                t1 = __shfl_sync(0xFFFFFFFFu, parr[f][1], srcA);
                af[0] = selOdd ? t1 : t0;
                t0 = __shfl_sync(0xFFFFFFFFu, parr[f][2], srcA);
                t1 = __shfl_sync(0xFFFFFFFFu, parr[f][3], srcA);
                af[1] = selOdd ? t1 : t0;
                t0 = __shfl_sync(0xFFFFFFFFu, parr[f][0], srcB);
                t1 = __shfl_sync(0xFFFFFFFFu, parr[f][1], srcB);
                af[2] = selOdd ? t1 : t0;
                t0 = __shfl_sync(0xFFFFFFFFu, parr[f][2], srcB);
                t1 = __shfl_sync(0xFFFFFFFFu, parr[f][3], srcB);
                af[3] = selOdd ? t1 : t0;
            }
            uint32_t chV = ((uint32_t)(8*wn + 2*f) + fchkB) ^ fsw;
#pragma unroll
            for (int g = 0; g < 4; g++) {
                uint32_t vfr[4];
                ldsm4(vfr, bufb + BUF_V + ((uint32_t)(16*g) + frowB)*256u + (chV << 4));
                mma_tf32(oacc[2*g + 0], af, &vfr[0]);
                mma_tf32(oacc[2*g + 1], af, &vfr[2]);
            }
        }
        __syncthreads();

        // prefetch tile t+2 into the buffer just freed
        if (t < 14 && tid == 0) {
            int img = bI*16 + t + 2;
            uint32_t dstb = sb + (idx ? SM_BUF1 : SM_BUF0);
            MBAR_EXPECT(mb[idx], BUF_BYTES);
            bulk_cp(dstb + BUF_KH,   g_kh   + (size_t)img*4096, 8192, mb[idx]);
            bulk_cp(dstb + BUF_KL,   g_kl   + (size_t)img*4096, 8192, mb[idx]);
            bulk_cp(dstb + BUF_KAUG, g_kaug + (size_t)img*1536, 3072, mb[idx]);
            bulk_cp(dstb + BUF_V,    g_vT   + (size_t)img*4096, 16384, mb[idx]);
        }
    }

    // ---- denominator reduction (4 lanes of each quad share rows) ----
#pragma unroll
    for (int off = 1; off < 4; off <<= 1)
#pragma unroll
        for (int h = 0; h < 2; h++)
            dsum[h] += __shfl_xor_sync(0xFFFFFFFFu, dsum[h], off);
    if ((lane & 3) == 0)
#pragma unroll
        for (int h = 0; h < 2; h++)
            sDen[wn][wm*16 + (lane >> 2) + 8*h] = dsum[h];

    // ---- O cross-warp (wn) reduction via smem (reuse BUF0 region) ----
    float* sRed = (float*)(dyn + SM_BUF0);
    int rloc = lane >> 2;
    if (wn == 1) {
#pragma unroll
        for (int nd = 0; nd < 8; nd++) {
            int col = nd*8 + 2*jj;
            *(float2*)&sRed[(wm*16 + rloc)*RED_STRIDE + col]     = make_float2(oacc[nd][0], oacc[nd][1]);
            *(float2*)&sRed[(wm*16 + rloc + 8)*RED_STRIDE + col] = make_float2(oacc[nd][2], oacc[nd][3]);
        }
    }
    __syncthreads();

    if (wn == 0) {
        float inv0 = 1.0f / (sDen[0][wm*16 + rloc]     + sDen[1][wm*16 + rloc]);
        float inv1 = 1.0f / (sDen[0][wm*16 + rloc + 8] + sDen[1][wm*16 + rloc + 8]);
#pragma unroll
        for (int nd = 0; nd < 8; nd++) {
            int col = nd*8 + 2*jj;
            float2 p0 = *(float2*)&sRed[(wm*16 + rloc)*RED_STRIDE + col];
            float2 p1 = *(float2*)&sRed[(wm*16 + rloc + 8)*RED_STRIDE + col];
            float2 o0, o1;
            o0.x = (oacc[nd][0] + p0.x) * inv0;
            o0.y = (oacc[nd][1] + p0.y) * inv0;
            o1.x = (oacc[nd][2] + p1.x) * inv1;
            o1.y = (oacc[nd][3] + p1.y) * inv1;
            int row0 = nbase + wm*16 + rloc;
            *(float2*)(g_kern + ((size_t)bI*Nn + row0)*64 + col)     = o0;
            *(float2*)(g_kern + ((size_t)bI*Nn + row0 + 8)*64 + col) = o1;
        }
    }
}

// ---------------------------------------------------------------------------
// Output MLP: out = relu(concat(points1, kern) @ Wo + bo)
// ---------------------------------------------------------------------------
__global__ __launch_bounds__(256) void mlp_kernel(
    const float* __restrict__ p1, const float* __restrict__ Wo,
    const float* __restrict__ bo, float* __restrict__ out)
{
    __shared__ float sA[64*64];
    __shared__ float sB[64*128];
    int tid = threadIdx.x;
    int rowbase = blockIdx.x * 64;
    int ty = tid >> 4, tx = tid & 15;
    int r0 = ty*4, c0 = tx*4;
    int rx[4], rb[4];
#pragma unroll
    for (int i = 0; i < 4; i++) { rx[i] = (r0+i) & 15; rb[i] = (r0+i)*64; }

    float acc[4][8] = {};
#pragma unroll 1
    for (int ch = 0; ch < 2; ch++) {
        const float* Asrc = ch ? (const float*)g_kern : p1;
        __syncthreads();
#pragma unroll
        for (int p = 0; p < 4; p++) {
            int lin = tid + 256*p;
            int r = lin >> 4, c4 = lin & 15;
            float4 t = *(const float4*)(Asrc + (rowbase + r)*64 + c4*4);
            *(float4*)(sA + r*64 + ((c4 ^ (r & 15)) << 2)) = t;
        }
#pragma unroll
        for (int p = 0; p < 8; p++) {
            int lin = tid + 256*p;
            int r = lin >> 5, c4 = lin & 31;
            *(float4*)(sB + r*128 + c4*4) = *(const float4*)(Wo + (ch*64 + r)*128 + c4*4);
        }
        __syncthreads();

#pragma unroll
        for (int d4 = 0; d4 < 16; d4++) {
            float a[4][4], b1[4][4], b2[4][4];
#pragma unroll
            for (int i = 0; i < 4; i++) {
                float4 t = *(const float4*)(sA + rb[i] + ((d4 ^ rx[i]) << 2));
                a[i][0]=t.x; a[i][1]=t.y; a[i][2]=t.z; a[i][3]=t.w;
            }
#pragma unroll
            for (int k = 0; k < 4; k++) {
                float4 t = *(const float4*)(sB + (d4*4+k)*128 + c0);
                b1[k][0]=t.x; b1[k][1]=t.y; b1[k][2]=t.z; b1[k][3]=t.w;
                float4 u = *(const float4*)(sB + (d4*4+k)*128 + 64 + c0);
                b2[k][0]=u.x; b2[k][1]=u.y; b2[k][2]=u.z; b2[k][3]=u.w;
            }
#pragma unroll
            for (int k = 0; k < 4; k++)
#pragma unroll
                for (int i = 0; i < 4; i++)
#pragma unroll
                    for (int j = 0; j < 4; j++) {
                        acc[i][j]   = fmaf(a[i][k], b1[k][j], acc[i][j]);
                        acc[i][4+j] = fmaf(a[i][k], b2[k][j], acc[i][4+j]);
                    }
        }
    }

    float bov[8];
#pragma unroll
    for (int j = 0; j < 4; j++) { bov[j] = bo[c0+j]; bov[4+j] = bo[64+c0+j]; }
#pragma unroll
    for (int i = 0; i < 4; i++) {
        int grow = rowbase + r0 + i;
        float4 o1, o2;
        o1.x = fmaxf(acc[i][0]+bov[0], 0.0f);
        o1.y = fmaxf(acc[i][1]+bov[1], 0.0f);
        o1.z = fmaxf(acc[i][2]+bov[2], 0.0f);
        o1.w = fmaxf(acc[i][3]+bov[3], 0.0f);
        o2.x = fmaxf(acc[i][4]+bov[4], 0.0f);
        o2.y = fmaxf(acc[i][5]+bov[5], 0.0f);
        o2.z = fmaxf(acc[i][6]+bov[6], 0.0f);
        o2.w = fmaxf(acc[i][7]+bov[7], 0.0f);
        *(float4*)(out + grow*128 + c0) = o1;
        *(float4*)(out + grow*128 + 64 + c0) = o2;
    }
}

// ---------------------------------------------------------------------------
extern "C" void kernel_launch(void* const* d_in, const int* in_sizes, int n_in,
                              void* d_out, int out_size)
{
    const float* xyz1 = (const float*)d_in[0];
    const float* xyz2 = (const float*)d_in[1];
    const float* p1   = (const float*)d_in[2];
    const float* p2   = (const float*)d_in[3];
    const float* Wq   = (const float*)d_in[4];
    const float* Wk   = (const float*)d_in[5];
    const float* Wv   = (const float*)d_in[6];
    const float* gm   = (const float*)d_in[7];
    const float* Wo   = (const float*)d_in[8];
    const float* bo   = (const float*)d_in[9];
    float* out = (float*)d_out;

    void *dqh, *dql, *dkh, *dkl, *dvT;
    cudaGetSymbolAddress(&dqh, g_qh);
    cudaGetSymbolAddress(&dql, g_ql);
    cudaGetSymbolAddress(&dkh, g_kh);
    cudaGetSymbolAddress(&dkl, g_kl);
    cudaGetSymbolAddress(&dvT, g_vT);

    aug_kernel<<<(Bb*Nn + Bb*Mm + 255)/256, 256>>>(xyz1, xyz2, gm);
    proj_kernel<0><<<(Bb*Nn)/64, 256>>>(p1, Wq, dqh, dql);
    proj_kernel<1><<<(Bb*Mm)/64, 256>>>(p2, Wk, dkh, dkl);
    proj_kernel<2><<<(Bb*Mm)/64, 256>>>(p2, Wv, dvT, nullptr);

    cudaFuncSetAttribute(attn_mma_kernel, cudaFuncAttributeMaxDynamicSharedMemorySize, SM_TOTAL);
    attn_mma_kernel<<<dim3(Nn/64, Bb), 256, SM_TOTAL>>>();

    mlp_kernel<<<(Bb*Nn)/64, 256>>>(p1, Wo, bo, out);
}